// round 2
// baseline (speedup 1.0000x reference)
#include <cuda_runtime.h>

#define NH 12
#define HD 64
#define HID 768
#define BSC 8        // cache0 batch
#define FULLB 240
#define LQ 32        // query length
#define LEN0 512
#define LEN1 128
#define TOTKV 672
#define MROWS (FULLB*LQ)   // 7680

// Scratch: q,k,v in (B, H, L, h) layout. 3 * 23.6 MB.
__device__ float g_q[FULLB*NH*LQ*HD];
__device__ float g_k[FULLB*NH*LQ*HD];
__device__ float g_v[FULLB*NH*LQ*HD];

// ---------------------------------------------------------------------------
// QKV GEMM: C(7680x768) = A(7680x768) @ W(768x768) + bias, for q/k/v
// 128x128 tile, BK=8, 256 threads, 8x8 microtile. Output scattered to
// (B,H,L,h) layout in scratch.
// ---------------------------------------------------------------------------
__global__ __launch_bounds__(256) void qkv_gemm(
    const float* __restrict__ A,
    const float* __restrict__ Wq, const float* __restrict__ bq,
    const float* __restrict__ Wk, const float* __restrict__ bk,
    const float* __restrict__ Wv, const float* __restrict__ bv)
{
    const float* W; const float* bias; float* out;
    if (blockIdx.z == 0)      { W = Wq; bias = bq; out = g_q; }
    else if (blockIdx.z == 1) { W = Wk; bias = bk; out = g_k; }
    else                      { W = Wv; bias = bv; out = g_v; }

    __shared__ float As[8][128];   // As[k][m] (A tile transposed)
    __shared__ float Bs[8][128];   // Bs[k][n]

    const int tid = threadIdx.x;
    const int tx = tid & 15;       // 0..15 -> n
    const int ty = tid >> 4;       // 0..15 -> m
    const int m0 = blockIdx.x * 128;
    const int n0 = blockIdx.y * 128;

    // A-load mapping: 128 rows x 2 float4
    const int la_row = tid >> 1;          // 0..127
    const int la_c4  = (tid & 1) * 4;     // 0 or 4
    // B-load mapping: 8 rows x 32 float4
    const int lb_row = tid >> 5;          // 0..7
    const int lb_c4  = (tid & 31) * 4;    // 0..124

    float acc[8][8];
    #pragma unroll
    for (int i = 0; i < 8; i++)
        #pragma unroll
        for (int j = 0; j < 8; j++) acc[i][j] = 0.f;

    for (int k0 = 0; k0 < HID; k0 += 8) {
        float4 a4 = *(const float4*)(A + (size_t)(m0 + la_row) * HID + k0 + la_c4);
        float4 b4 = *(const float4*)(W + (size_t)(k0 + lb_row) * HID + n0 + lb_c4);
        __syncthreads();
        As[la_c4 + 0][la_row] = a4.x;
        As[la_c4 + 1][la_row] = a4.y;
        As[la_c4 + 2][la_row] = a4.z;
        As[la_c4 + 3][la_row] = a4.w;
        *(float4*)(&Bs[lb_row][lb_c4]) = b4;
        __syncthreads();
        #pragma unroll
        for (int kk = 0; kk < 8; kk++) {
            float4 a0 = *(const float4*)(&As[kk][ty * 8]);
            float4 a1 = *(const float4*)(&As[kk][ty * 8 + 4]);
            float4 b0 = *(const float4*)(&Bs[kk][tx * 8]);
            float4 b1 = *(const float4*)(&Bs[kk][tx * 8 + 4]);
            float av[8] = {a0.x, a0.y, a0.z, a0.w, a1.x, a1.y, a1.z, a1.w};
            float bv2[8] = {b0.x, b0.y, b0.z, b0.w, b1.x, b1.y, b1.z, b1.w};
            #pragma unroll
            for (int i = 0; i < 8; i++)
                #pragma unroll
                for (int j = 0; j < 8; j++)
                    acc[i][j] += av[i] * bv2[j];
        }
    }

    // Epilogue: bias + scatter to (B,H,L,h)
    #pragma unroll
    for (int i = 0; i < 8; i++) {
        int m = m0 + ty * 8 + i;
        int b = m >> 5;            // /32
        int l = m & 31;
        #pragma unroll
        for (int j = 0; j < 8; j++) {
            int n = n0 + tx * 8 + j;
            int h = n >> 6;
            int d = n & 63;
            out[(((size_t)b * NH + h) * LQ + l) * HD + d] = acc[i][j] + bias[n];
        }
    }
}

// ---------------------------------------------------------------------------
// Attention: one CTA per (b,h). Flash-style streaming softmax over 21 tiles
// of 32 KV positions: 16 from cache0[b%8], 4 from cache1[b], 1 self.
// 256 threads: thread = (row r = tid>>3, group g = tid&7); each thread owns
// output cols [g*8, g*8+8) of row r.
// ---------------------------------------------------------------------------
__global__ __launch_bounds__(256) void attn_kernel(
    const float* __restrict__ c0k, const float* __restrict__ c0v,
    const float* __restrict__ c1k, const float* __restrict__ c1v,
    const float* __restrict__ mask, float* __restrict__ out)
{
    const int bh = blockIdx.x;
    const int b = bh / NH;
    const int h = bh % NH;

    __shared__ float q_s[LQ * 68];     // padded rows (68 = 64+4)
    __shared__ float k_s[LQ * 68];
    __shared__ float v_s[LQ * HD];
    __shared__ float p_s[LQ * 33];     // padded
    __shared__ float mask_s[TOTKV];

    const int tid = threadIdx.x;
    const int r = tid >> 3;
    const int g = tid & 7;

    // load q (32x64) into padded smem; 512 float4 total
    {
        const float* qp = g_q + (size_t)bh * (LQ * HD);
        #pragma unroll
        for (int it = 0; it < 2; it++) {
            int i = tid + it * 256;
            int row = i >> 4;
            int c4 = i & 15;
            *(float4*)(q_s + row * 68 + c4 * 4) = ((const float4*)(qp + row * HD))[c4];
        }
    }
    for (int i = tid; i < TOTKV; i += 256)
        mask_s[i] = mask[(size_t)b * TOTKV + i];

    float m_r = -1e30f, l_r = 0.f;
    float o[8];
    #pragma unroll
    for (int cc = 0; cc < 8; cc++) o[cc] = 0.f;

    for (int t = 0; t < 21; ++t) {
        const float* kp; const float* vp; int kvbase;
        if (t < 16) {
            size_t off = (((size_t)(b % BSC) * NH + h) * LEN0 + t * 32) * HD;
            kp = c0k + off; vp = c0v + off; kvbase = t * 32;
        } else if (t < 20) {
            size_t off = (((size_t)b * NH + h) * LEN1 + (t - 16) * 32) * HD;
            kp = c1k + off; vp = c1v + off; kvbase = LEN0 + (t - 16) * 32;
        } else {
            size_t off = (size_t)bh * (LQ * HD);
            kp = g_k + off; vp = g_v + off; kvbase = LEN0 + LEN1;
        }

        __syncthreads();   // prior PV done before overwriting k_s/v_s
        #pragma unroll
        for (int it = 0; it < 2; it++) {
            int i = tid + it * 256;
            int row = i >> 4;
            int c4 = i & 15;
            float4 kf = ((const float4*)(kp + row * HD))[c4];
            *(float4*)(k_s + row * 68 + c4 * 4) = kf;
            ((float4*)(v_s + row * HD))[c4] = ((const float4*)(vp + row * HD))[c4];
        }
        __syncthreads();

        // scores: thread computes j = g + jj*8, jj=0..3
        float s0 = 0.f, s1 = 0.f, s2 = 0.f, s3 = 0.f;
        {
            const float4* q4  = (const float4*)(q_s + r * 68);
            const float4* k40 = (const float4*)(k_s + (g + 0) * 68);
            const float4* k41 = (const float4*)(k_s + (g + 8) * 68);
            const float4* k42 = (const float4*)(k_s + (g + 16) * 68);
            const float4* k43 = (const float4*)(k_s + (g + 24) * 68);
            #pragma unroll
            for (int kk = 0; kk < 16; kk++) {
                float4 qv = q4[kk];
                float4 kv;
                kv = k40[kk]; s0 += qv.x*kv.x + qv.y*kv.y + qv.z*kv.z + qv.w*kv.w;
                kv = k41[kk]; s1 += qv.x*kv.x + qv.y*kv.y + qv.z*kv.z + qv.w*kv.w;
                kv = k42[kk]; s2 += qv.x*kv.x + qv.y*kv.y + qv.z*kv.z + qv.w*kv.w;
                kv = k43[kk]; s3 += qv.x*kv.x + qv.y*kv.y + qv.z*kv.z + qv.w*kv.w;
            }
        }
        s0 = s0 * 0.125f + mask_s[kvbase + g];
        s1 = s1 * 0.125f + mask_s[kvbase + g + 8];
        s2 = s2 * 0.125f + mask_s[kvbase + g + 16];
        s3 = s3 * 0.125f + mask_s[kvbase + g + 24];

        float tmax = fmaxf(fmaxf(s0, s1), fmaxf(s2, s3));
        #pragma unroll
        for (int d = 1; d < 8; d <<= 1)
            tmax = fmaxf(tmax, __shfl_xor_sync(0xffffffffu, tmax, d));
        float m_new = fmaxf(m_r, tmax);
        float alpha = __expf(m_r - m_new);

        float p0 = __expf(s0 - m_new);
        float p1 = __expf(s1 - m_new);
        float p2 = __expf(s2 - m_new);
        float p3 = __expf(s3 - m_new);
        p_s[r * 33 + g]      = p0;
        p_s[r * 33 + g + 8]  = p1;
        p_s[r * 33 + g + 16] = p2;
        p_s[r * 33 + g + 24] = p3;
        float psum = p0 + p1 + p2 + p3;
        #pragma unroll
        for (int d = 1; d < 8; d <<= 1)
            psum += __shfl_xor_sync(0xffffffffu, psum, d);
        l_r = l_r * alpha + psum;
        m_r = m_new;

        #pragma unroll
        for (int cc = 0; cc < 8; cc++) o[cc] *= alpha;

        __syncthreads();   // p_s visible (and keeps tile phases aligned)

        // PV: o[cc] += sum_j p[r][j] * v[j][g*8 + cc]
        #pragma unroll
        for (int j = 0; j < 32; j++) {
            float p = p_s[r * 33 + j];
            float4 v0 = *(const float4*)(v_s + j * HD + g * 8);
            float4 v1 = *(const float4*)(v_s + j * HD + g * 8 + 4);
            o[0] += p * v0.x; o[1] += p * v0.y; o[2] += p * v0.z; o[3] += p * v0.w;
            o[4] += p * v1.x; o[5] += p * v1.y; o[6] += p * v1.z; o[7] += p * v1.w;
        }
    }

    float invl = 1.f / l_r;
    #pragma unroll
    for (int cc = 0; cc < 8; cc++) o[cc] *= invl;

    float* op = out + ((size_t)(b * LQ + r)) * HID + h * HD + g * 8;
    *(float4*)(op)     = make_float4(o[0], o[1], o[2], o[3]);
    *(float4*)(op + 4) = make_float4(o[4], o[5], o[6], o[7]);
}

extern "C" void kernel_launch(void* const* d_in, const int* in_sizes, int n_in,
                              void* d_out, int out_size)
{
    const float* hs   = (const float*)d_in[0];
    const float* mask = (const float*)d_in[1];
    const float* c0k  = (const float*)d_in[2];
    const float* c0v  = (const float*)d_in[3];
    const float* c1k  = (const float*)d_in[4];
    const float* c1v  = (const float*)d_in[5];
    const float* Wq   = (const float*)d_in[6];
    const float* bq   = (const float*)d_in[7];
    const float* Wk   = (const float*)d_in[8];
    const float* bk   = (const float*)d_in[9];
    const float* Wv   = (const float*)d_in[10];
    const float* bv   = (const float*)d_in[11];
    float* out = (float*)d_out;

    dim3 ggrid(MROWS / 128, HID / 128, 3);   // (60, 6, 3)
    qkv_gemm<<<ggrid, 256>>>(hs, Wq, bq, Wk, bk, Wv, bv);
    attn_kernel<<<FULLB * NH, 256>>>(c0k, c0v, c1k, c1v, mask, out);
}

// round 3
// speedup vs baseline: 1.6650x; 1.6650x over previous
#include <cuda_runtime.h>

#define NH 12
#define HD 64
#define HID 768
#define BSC 8        // cache0 batch
#define FULLB 240
#define LQ 32        // query length
#define LEN0 512
#define LEN1 128
#define TOTKV 672
#define MROWS (FULLB*LQ)   // 7680

// Scratch: q,k,v in (B, H, L, h) layout.
__device__ float g_q[FULLB*NH*LQ*HD];
__device__ float g_k[FULLB*NH*LQ*HD];
__device__ float g_v[FULLB*NH*LQ*HD];

// ---------------------------------------------------------------------------
// QKV GEMM: C(7680x768) = A(7680x768) @ W(768x768) + bias, for q/k/v
// ---------------------------------------------------------------------------
__global__ __launch_bounds__(256) void qkv_gemm(
    const float* __restrict__ A,
    const float* __restrict__ Wq, const float* __restrict__ bq,
    const float* __restrict__ Wk, const float* __restrict__ bk,
    const float* __restrict__ Wv, const float* __restrict__ bv)
{
    const float* W; const float* bias; float* out;
    if (blockIdx.z == 0)      { W = Wq; bias = bq; out = g_q; }
    else if (blockIdx.z == 1) { W = Wk; bias = bk; out = g_k; }
    else                      { W = Wv; bias = bv; out = g_v; }

    __shared__ float As[8][128];   // As[k][m]
    __shared__ float Bs[8][128];   // Bs[k][n]

    const int tid = threadIdx.x;
    const int tx = tid & 15;
    const int ty = tid >> 4;
    const int m0 = blockIdx.x * 128;
    const int n0 = blockIdx.y * 128;

    const int la_row = tid >> 1;
    const int la_c4  = (tid & 1) * 4;
    const int lb_row = tid >> 5;
    const int lb_c4  = (tid & 31) * 4;

    float acc[8][8];
    #pragma unroll
    for (int i = 0; i < 8; i++)
        #pragma unroll
        for (int j = 0; j < 8; j++) acc[i][j] = 0.f;

    for (int k0 = 0; k0 < HID; k0 += 8) {
        float4 a4 = *(const float4*)(A + (size_t)(m0 + la_row) * HID + k0 + la_c4);
        float4 b4 = *(const float4*)(W + (size_t)(k0 + lb_row) * HID + n0 + lb_c4);
        __syncthreads();
        As[la_c4 + 0][la_row] = a4.x;
        As[la_c4 + 1][la_row] = a4.y;
        As[la_c4 + 2][la_row] = a4.z;
        As[la_c4 + 3][la_row] = a4.w;
        *(float4*)(&Bs[lb_row][lb_c4]) = b4;
        __syncthreads();
        #pragma unroll
        for (int kk = 0; kk < 8; kk++) {
            float4 a0 = *(const float4*)(&As[kk][ty * 8]);
            float4 a1 = *(const float4*)(&As[kk][ty * 8 + 4]);
            float4 b0 = *(const float4*)(&Bs[kk][tx * 8]);
            float4 b1 = *(const float4*)(&Bs[kk][tx * 8 + 4]);
            float av[8] = {a0.x, a0.y, a0.z, a0.w, a1.x, a1.y, a1.z, a1.w};
            float bv2[8] = {b0.x, b0.y, b0.z, b0.w, b1.x, b1.y, b1.z, b1.w};
            #pragma unroll
            for (int i = 0; i < 8; i++)
                #pragma unroll
                for (int j = 0; j < 8; j++)
                    acc[i][j] += av[i] * bv2[j];
        }
    }

    #pragma unroll
    for (int i = 0; i < 8; i++) {
        int m = m0 + ty * 8 + i;
        int b = m >> 5;
        int l = m & 31;
        #pragma unroll
        for (int j = 0; j < 8; j++) {
            int n = n0 + tx * 8 + j;
            int h = n >> 6;
            int d = n & 63;
            out[(((size_t)b * NH + h) * LQ + l) * HD + d] = acc[i][j] + bias[n];
        }
    }
}

// ---------------------------------------------------------------------------
// Attention: one CTA per (b,h), 128 threads, KV tiles of 64 rows.
// Thread grid 8x16: ty=tid>>4 (rows ty+8i, i=0..3), tx=tid&15
// (score cols tx+16jj, PV output cols tx*4..tx*4+3).
// 4x4 register microtiles in both GEMM loops; P aliases the K smem tile.
// ---------------------------------------------------------------------------
#define SDK 68   // k/p smem row stride (floats)
#define SDQ 68

__global__ __launch_bounds__(128) void attn_kernel(
    const float* __restrict__ c0k, const float* __restrict__ c0v,
    const float* __restrict__ c1k, const float* __restrict__ c1v,
    const float* __restrict__ mask, float* __restrict__ out)
{
    const int bh = blockIdx.x;
    const int b = bh / NH;
    const int h = bh % NH;

    __shared__ float q_s[LQ * SDQ];      // 2176 f
    __shared__ float kp_s[64 * SDK];     // K tile; reused for P (rows 0..31)
    __shared__ float v_s[64 * HD];       // 4096 f
    __shared__ float mask_s[TOTKV];      // 672 f

    const int tid = threadIdx.x;
    const int ty = tid >> 4;   // 0..7
    const int tx = tid & 15;   // 0..15

    // load q (32x64) once: 512 float4 over 128 threads
    {
        const float* qp = g_q + (size_t)bh * (LQ * HD);
        #pragma unroll
        for (int it = 0; it < 4; it++) {
            int i = tid + it * 128;
            int row = i >> 4;
            int c4 = (i & 15) * 4;
            *(float4*)(q_s + row * SDQ + c4) = *(const float4*)(qp + row * HD + c4);
        }
    }
    for (int i = tid; i < TOTKV; i += 128)
        mask_s[i] = mask[(size_t)b * TOTKV + i];

    float m_r[4], l_r[4];
    float o[4][4];
    #pragma unroll
    for (int i = 0; i < 4; i++) {
        m_r[i] = -1e30f; l_r[i] = 0.f;
        #pragma unroll
        for (int c = 0; c < 4; c++) o[i][c] = 0.f;
    }

    for (int t = 0; t < 11; ++t) {
        const float* kp; const float* vp; int rows, kvbase;
        if (t < 8) {
            size_t off = (((size_t)(b % BSC) * NH + h) * LEN0 + t * 64) * HD;
            kp = c0k + off; vp = c0v + off; rows = 64; kvbase = t * 64;
        } else if (t < 10) {
            size_t off = (((size_t)b * NH + h) * LEN1 + (t - 8) * 64) * HD;
            kp = c1k + off; vp = c1v + off; rows = 64; kvbase = LEN0 + (t - 8) * 64;
        } else {
            size_t off = (size_t)bh * (LQ * HD);
            kp = g_k + off; vp = g_v + off; rows = 32; kvbase = LEN0 + LEN1;
        }

        __syncthreads();   // prior PV done before overwriting kp_s/v_s
        {
            int nld = rows * 16 / 128;   // 8 or 4
            for (int it = 0; it < nld; it++) {
                int i = tid + it * 128;
                int row = i >> 4;
                int c4 = (i & 15) * 4;
                *(float4*)(kp_s + row * SDK + c4) = *(const float4*)(kp + row * HD + c4);
                *(float4*)(v_s + row * HD + c4)  = *(const float4*)(vp + row * HD + c4);
            }
        }
        __syncthreads();

        // ---- scores: s[i][jj] = q[ty+8i] . k[tx+16jj] ----
        float s[4][4];
        #pragma unroll
        for (int i = 0; i < 4; i++)
            #pragma unroll
            for (int j = 0; j < 4; j++) s[i][j] = 0.f;

        #pragma unroll
        for (int kk = 0; kk < 16; kk++) {
            float4 qv[4], kv[4];
            #pragma unroll
            for (int i = 0; i < 4; i++)
                qv[i] = *(const float4*)(q_s + (ty + 8 * i) * SDQ + kk * 4);
            #pragma unroll
            for (int j = 0; j < 4; j++)
                kv[j] = *(const float4*)(kp_s + (tx + 16 * j) * SDK + kk * 4);
            #pragma unroll
            for (int i = 0; i < 4; i++)
                #pragma unroll
                for (int j = 0; j < 4; j++)
                    s[i][j] += qv[i].x * kv[j].x + qv[i].y * kv[j].y
                             + qv[i].z * kv[j].z + qv[i].w * kv[j].w;
        }

        // ---- online softmax (per row i) ----
        #pragma unroll
        for (int i = 0; i < 4; i++) {
            #pragma unroll
            for (int j = 0; j < 4; j++) {
                int jc = tx + 16 * j;
                if (jc < rows)
                    s[i][j] = s[i][j] * 0.125f + mask_s[kvbase + jc];
                else
                    s[i][j] = -1e30f;
            }
            float rmax = fmaxf(fmaxf(s[i][0], s[i][1]), fmaxf(s[i][2], s[i][3]));
            #pragma unroll
            for (int d = 1; d < 16; d <<= 1)
                rmax = fmaxf(rmax, __shfl_xor_sync(0xffffffffu, rmax, d));
            float m_new = fmaxf(m_r[i], rmax);
            float alpha = __expf(m_r[i] - m_new);
            float psum = 0.f;
            #pragma unroll
            for (int j = 0; j < 4; j++) {
                s[i][j] = __expf(s[i][j] - m_new);
                psum += s[i][j];
            }
            #pragma unroll
            for (int d = 1; d < 16; d <<= 1)
                psum += __shfl_xor_sync(0xffffffffu, psum, d);
            l_r[i] = l_r[i] * alpha + psum;
            m_r[i] = m_new;
            #pragma unroll
            for (int c = 0; c < 4; c++) o[i][c] *= alpha;
        }

        __syncthreads();   // everyone done reading K from kp_s
        // store P into kp_s (rows 0..31)
        #pragma unroll
        for (int i = 0; i < 4; i++)
            #pragma unroll
            for (int j = 0; j < 4; j++)
                kp_s[(ty + 8 * i) * SDK + tx + 16 * j] = s[i][j];
        __syncthreads();

        // ---- PV: o[i][c] += sum_j p[r][j] * v[j][tx*4+c] ----
        #pragma unroll
        for (int jg = 0; jg < 16; jg++) {
            float4 pv[4];
            #pragma unroll
            for (int i = 0; i < 4; i++)
                pv[i] = *(const float4*)(kp_s + (ty + 8 * i) * SDK + jg * 4);
            float4 v0 = *(const float4*)(v_s + (jg * 4 + 0) * HD + tx * 4);
            float4 v1 = *(const float4*)(v_s + (jg * 4 + 1) * HD + tx * 4);
            float4 v2 = *(const float4*)(v_s + (jg * 4 + 2) * HD + tx * 4);
            float4 v3 = *(const float4*)(v_s + (jg * 4 + 3) * HD + tx * 4);
            #pragma unroll
            for (int i = 0; i < 4; i++) {
                o[i][0] += pv[i].x * v0.x + pv[i].y * v1.x + pv[i].z * v2.x + pv[i].w * v3.x;
                o[i][1] += pv[i].x * v0.y + pv[i].y * v1.y + pv[i].z * v2.y + pv[i].w * v3.y;
                o[i][2] += pv[i].x * v0.z + pv[i].y * v1.z + pv[i].z * v2.z + pv[i].w * v3.z;
                o[i][3] += pv[i].x * v0.w + pv[i].y * v1.w + pv[i].z * v2.w + pv[i].w * v3.w;
            }
        }
    }

    // normalize + store
    #pragma unroll
    for (int i = 0; i < 4; i++) {
        float invl = 1.f / l_r[i];
        int r = ty + 8 * i;
        float* op = out + ((size_t)(b * LQ + r)) * HID + h * HD + tx * 4;
        *(float4*)op = make_float4(o[i][0] * invl, o[i][1] * invl,
                                   o[i][2] * invl, o[i][3] * invl);
    }
}

extern "C" void kernel_launch(void* const* d_in, const int* in_sizes, int n_in,
                              void* d_out, int out_size)
{
    const float* hs   = (const float*)d_in[0];
    const float* mask = (const float*)d_in[1];
    const float* c0k  = (const float*)d_in[2];
    const float* c0v  = (const float*)d_in[3];
    const float* c1k  = (const float*)d_in[4];
    const float* c1v  = (const float*)d_in[5];
    const float* Wq   = (const float*)d_in[6];
    const float* bq   = (const float*)d_in[7];
    const float* Wk   = (const float*)d_in[8];
    const float* bk   = (const float*)d_in[9];
    const float* Wv   = (const float*)d_in[10];
    const float* bv   = (const float*)d_in[11];
    float* out = (float*)d_out;

    dim3 ggrid(MROWS / 128, HID / 128, 3);   // (60, 6, 3)
    qkv_gemm<<<ggrid, 256>>>(hs, Wq, bq, Wk, bk, Wv, bv);
    attn_kernel<<<FULLB * NH, 128>>>(c0k, c0v, c1k, c1v, mask, out);
}

// round 6
// speedup vs baseline: 3.0679x; 1.8426x over previous
#include <cuda_runtime.h>
#include <cstdint>

#define NH 12
#define HD 64
#define HID 768
#define BSC 8
#define FULLB 240
#define LQ 32
#define LEN0 512
#define LEN1 128
#define TOTKV 672
#define MROWS (FULLB*LQ)   // 7680

// Scratch
__device__ float g_q[FULLB*NH*LQ*HD];
__device__ float g_k[FULLB*NH*LQ*HD];
__device__ float g_v[FULLB*NH*LQ*HD];
__device__ float g_wt[3*HID*HID];     // Wt[n][k] = W[k][n]

// ---------------------------------------------------------------------------
// Weight transpose: Wt[n][k] = W[k][n]
// ---------------------------------------------------------------------------
__global__ __launch_bounds__(256) void transpose_w(
    const float* __restrict__ Wq, const float* __restrict__ Wk, const float* __restrict__ Wv)
{
    const float* W = blockIdx.z == 0 ? Wq : blockIdx.z == 1 ? Wk : Wv;
    float* Wt = g_wt + (size_t)blockIdx.z * HID * HID;
    __shared__ float ts[32][33];
    int tx = threadIdx.x, ty = threadIdx.y;
    int x = blockIdx.x * 32 + tx;
    int y0 = blockIdx.y * 32;
    #pragma unroll
    for (int i = 0; i < 4; i++)
        ts[ty + 8 * i][tx] = W[(size_t)(y0 + ty + 8 * i) * HID + x];
    __syncthreads();
    int x2 = blockIdx.y * 32 + tx;
    int y2 = blockIdx.x * 32;
    #pragma unroll
    for (int i = 0; i < 4; i++)
        Wt[(size_t)(y2 + ty + 8 * i) * HID + x2] = ts[tx][ty + 8 * i];
}

// ---------------------------------------------------------------------------
// TF32 mma.sync QKV GEMM: C(7680x768) = A @ W + bias.
// CTA 128x128, 8 warps (2m x 4n), warp tile 64x32, m16n8k8 fragments.
// ---------------------------------------------------------------------------
#define KB 32
#define SAS 36   // smem row stride (floats): (4g+tig) mod 32 distinct -> conflict-free

__device__ __forceinline__ void mma_tf32(float* c, uint32_t a0, uint32_t a1,
                                         uint32_t a2, uint32_t a3,
                                         uint32_t b0, uint32_t b1) {
    asm volatile(
        "mma.sync.aligned.m16n8k8.row.col.f32.tf32.tf32.f32 "
        "{%0,%1,%2,%3}, {%4,%5,%6,%7}, {%8,%9}, {%0,%1,%2,%3};"
        : "+f"(c[0]), "+f"(c[1]), "+f"(c[2]), "+f"(c[3])
        : "r"(a0), "r"(a1), "r"(a2), "r"(a3), "r"(b0), "r"(b1));
}

__global__ __launch_bounds__(256) void qkv_gemm_mma(
    const float* __restrict__ A,
    const float* __restrict__ bq, const float* __restrict__ bk, const float* __restrict__ bv)
{
    __shared__ float As[128 * SAS];
    __shared__ float Bs[128 * SAS];

    const int tid = threadIdx.x;
    const int wid = tid >> 5;
    const int lane = tid & 31;
    const int g = lane >> 2;       // groupID 0..7
    const int tig = lane & 3;      // thread-in-group 0..3
    const int wm = wid & 1;        // 2 m-warps
    const int wn = wid >> 1;       // 4 n-warps

    const int z = blockIdx.z;
    const float* bias = z == 0 ? bq : z == 1 ? bk : bv;
    float* out = z == 0 ? g_q : z == 1 ? g_k : g_v;
    const float* Wt = g_wt + (size_t)z * HID * HID;
    const int m0 = blockIdx.x * 128;
    const int n0 = blockIdx.y * 128;

    float c[4][4][4];
    #pragma unroll
    for (int mt = 0; mt < 4; mt++)
        #pragma unroll
        for (int nt = 0; nt < 4; nt++)
            #pragma unroll
            for (int q = 0; q < 4; q++) c[mt][nt][q] = 0.f;

    const int lrow = tid >> 1;            // 0..127
    const int lc4  = (tid & 1) * 4;       // A/B fill: 128 rows x 8 float4, 4 iters... 
    // Actually: 128 rows * 8 float4 = 1024 loads over 256 threads -> 4 iters, i = tid + it*256
    for (int k0 = 0; k0 < HID; k0 += KB) {
        __syncthreads();
        #pragma unroll
        for (int it = 0; it < 4; it++) {
            int i = tid + it * 256;      // 0..1023
            int row = i >> 3;
            int c4 = (i & 7) * 4;
            *(float4*)(As + row * SAS + c4) =
                *(const float4*)(A  + (size_t)(m0 + row) * HID + k0 + c4);
            *(float4*)(Bs + row * SAS + c4) =
                *(const float4*)(Wt + (size_t)(n0 + row) * HID + k0 + c4);
        }
        __syncthreads();

        #pragma unroll
        for (int ks = 0; ks < 4; ks++) {
            const int kb = ks * 8;
            // B fragments for all 4 n-tiles
            uint32_t bf[4][2];
            #pragma unroll
            for (int nt = 0; nt < 4; nt++) {
                const float* bp = Bs + (wn * 32 + nt * 8 + g) * SAS + kb + tig;
                bf[nt][0] = __float_as_uint(bp[0]);
                bf[nt][1] = __float_as_uint(bp[4]);
            }
            #pragma unroll
            for (int mt = 0; mt < 4; mt++) {
                const float* ap0 = As + (wm * 64 + mt * 16 + g) * SAS + kb + tig;
                const float* ap1 = ap0 + 8 * SAS;
                uint32_t a0 = __float_as_uint(ap0[0]);
                uint32_t a1 = __float_as_uint(ap1[0]);
                uint32_t a2 = __float_as_uint(ap0[4]);
                uint32_t a3 = __float_as_uint(ap1[4]);
                #pragma unroll
                for (int nt = 0; nt < 4; nt++)
                    mma_tf32(c[mt][nt], a0, a1, a2, a3, bf[nt][0], bf[nt][1]);
            }
        }
    }

    // Epilogue: scatter to (B,H,L,h) with bias; rows g and g+8, col pairs.
    #pragma unroll
    for (int mt = 0; mt < 4; mt++) {
        int r0 = m0 + wm * 64 + mt * 16 + g;
        #pragma unroll
        for (int half = 0; half < 2; half++) {
            int r = r0 + half * 8;
            int b = r >> 5;
            int l = r & 31;
            float* obase = out + (((size_t)b * NH) * LQ + l) * HD;
            #pragma unroll
            for (int nt = 0; nt < 4; nt++) {
                int n = n0 + wn * 32 + nt * 8 + tig * 2;
                int h = n >> 6;
                int d = n & 63;
                float2 v;
                v.x = c[mt][nt][half * 2 + 0] + bias[n];
                v.y = c[mt][nt][half * 2 + 1] + bias[n + 1];
                *(float2*)(obase + (size_t)h * LQ * HD + d) = v;
            }
        }
    }
}

// ---------------------------------------------------------------------------
// Attention (R2-proven): one CTA per (b,h), 128 threads, KV tiles 64.
// ---------------------------------------------------------------------------
#define SDK 68
#define SDQ 68

__global__ __launch_bounds__(128) void attn_kernel(
    const float* __restrict__ c0k, const float* __restrict__ c0v,
    const float* __restrict__ c1k, const float* __restrict__ c1v,
    const float* __restrict__ mask, float* __restrict__ out)
{
    const int bh = blockIdx.x;
    const int b = bh / NH;
    const int h = bh % NH;

    __shared__ float q_s[LQ * SDQ];
    __shared__ float kp_s[64 * SDK];
    __shared__ float v_s[64 * HD];
    __shared__ float mask_s[TOTKV];

    const int tid = threadIdx.x;
    const int ty = tid >> 4;
    const int tx = tid & 15;

    {
        const float* qp = g_q + (size_t)bh * (LQ * HD);
        #pragma unroll
        for (int it = 0; it < 4; it++) {
            int i = tid + it * 128;
            int row = i >> 4;
            int c4 = (i & 15) * 4;
            *(float4*)(q_s + row * SDQ + c4) = *(const float4*)(qp + row * HD + c4);
        }
    }
    for (int i = tid; i < TOTKV; i += 128)
        mask_s[i] = mask[(size_t)b * TOTKV + i];

    float m_r[4], l_r[4];
    float o[4][4];
    #pragma unroll
    for (int i = 0; i < 4; i++) {
        m_r[i] = -1e30f; l_r[i] = 0.f;
        #pragma unroll
        for (int c = 0; c < 4; c++) o[i][c] = 0.f;
    }

    for (int t = 0; t < 11; ++t) {
        const float* kp; const float* vp; int rows, kvbase;
        if (t < 8) {
            size_t off = (((size_t)(b % BSC) * NH + h) * LEN0 + t * 64) * HD;
            kp = c0k + off; vp = c0v + off; rows = 64; kvbase = t * 64;
        } else if (t < 10) {
            size_t off = (((size_t)b * NH + h) * LEN1 + (t - 8) * 64) * HD;
            kp = c1k + off; vp = c1v + off; rows = 64; kvbase = LEN0 + (t - 8) * 64;
        } else {
            size_t off = (size_t)bh * (LQ * HD);
            kp = g_k + off; vp = g_v + off; rows = 32; kvbase = LEN0 + LEN1;
        }

        __syncthreads();
        {
            int nld = rows * 16 / 128;
            for (int it = 0; it < nld; it++) {
                int i = tid + it * 128;
                int row = i >> 4;
                int c4 = (i & 15) * 4;
                *(float4*)(kp_s + row * SDK + c4) = *(const float4*)(kp + row * HD + c4);
                *(float4*)(v_s + row * HD + c4)  = *(const float4*)(vp + row * HD + c4);
            }
        }
        __syncthreads();

        float s[4][4];
        #pragma unroll
        for (int i = 0; i < 4; i++)
            #pragma unroll
            for (int j = 0; j < 4; j++) s[i][j] = 0.f;

        #pragma unroll
        for (int kk = 0; kk < 16; kk++) {
            float4 qv[4], kv[4];
            #pragma unroll
            for (int i = 0; i < 4; i++)
                qv[i] = *(const float4*)(q_s + (ty + 8 * i) * SDQ + kk * 4);
            #pragma unroll
            for (int j = 0; j < 4; j++)
                kv[j] = *(const float4*)(kp_s + (tx + 16 * j) * SDK + kk * 4);
            #pragma unroll
            for (int i = 0; i < 4; i++)
                #pragma unroll
                for (int j = 0; j < 4; j++)
                    s[i][j] += qv[i].x * kv[j].x + qv[i].y * kv[j].y
                             + qv[i].z * kv[j].z + qv[i].w * kv[j].w;
        }

        #pragma unroll
        for (int i = 0; i < 4; i++) {
            #pragma unroll
            for (int j = 0; j < 4; j++) {
                int jc = tx + 16 * j;
                if (jc < rows)
                    s[i][j] = s[i][j] * 0.125f + mask_s[kvbase + jc];
                else
                    s[i][j] = -1e30f;
            }
            float rmax = fmaxf(fmaxf(s[i][0], s[i][1]), fmaxf(s[i][2], s[i][3]));
            #pragma unroll
            for (int d = 1; d < 16; d <<= 1)
                rmax = fmaxf(rmax, __shfl_xor_sync(0xffffffffu, rmax, d));
            float m_new = fmaxf(m_r[i], rmax);
            float alpha = __expf(m_r[i] - m_new);
            float psum = 0.f;
            #pragma unroll
            for (int j = 0; j < 4; j++) {
                s[i][j] = __expf(s[i][j] - m_new);
                psum += s[i][j];
            }
            #pragma unroll
            for (int d = 1; d < 16; d <<= 1)
                psum += __shfl_xor_sync(0xffffffffu, psum, d);
            l_r[i] = l_r[i] * alpha + psum;
            m_r[i] = m_new;
            #pragma unroll
            for (int c = 0; c < 4; c++) o[i][c] *= alpha;
        }

        __syncthreads();
        #pragma unroll
        for (int i = 0; i < 4; i++)
            #pragma unroll
            for (int j = 0; j < 4; j++)
                kp_s[(ty + 8 * i) * SDK + tx + 16 * j] = s[i][j];
        __syncthreads();

        #pragma unroll
        for (int jg = 0; jg < 16; jg++) {
            float4 pv[4];
            #pragma unroll
            for (int i = 0; i < 4; i++)
                pv[i] = *(const float4*)(kp_s + (ty + 8 * i) * SDK + jg * 4);
            float4 v0 = *(const float4*)(v_s + (jg * 4 + 0) * HD + tx * 4);
            float4 v1 = *(const float4*)(v_s + (jg * 4 + 1) * HD + tx * 4);
            float4 v2 = *(const float4*)(v_s + (jg * 4 + 2) * HD + tx * 4);
            float4 v3 = *(const float4*)(v_s + (jg * 4 + 3) * HD + tx * 4);
            #pragma unroll
            for (int i = 0; i < 4; i++) {
                o[i][0] += pv[i].x * v0.x + pv[i].y * v1.x + pv[i].z * v2.x + pv[i].w * v3.x;
                o[i][1] += pv[i].x * v0.y + pv[i].y * v1.y + pv[i].z * v2.y + pv[i].w * v3.y;
                o[i][2] += pv[i].x * v0.z + pv[i].y * v1.z + pv[i].z * v2.z + pv[i].w * v3.z;
                o[i][3] += pv[i].x * v0.w + pv[i].y * v1.w + pv[i].z * v2.w + pv[i].w * v3.w;
            }
        }
    }

    #pragma unroll
    for (int i = 0; i < 4; i++) {
        float invl = 1.f / l_r[i];
        int r = ty + 8 * i;
        float* op = out + ((size_t)(b * LQ + r)) * HID + h * HD + tx * 4;
        *(float4*)op = make_float4(o[i][0] * invl, o[i][1] * invl,
                                   o[i][2] * invl, o[i][3] * invl);
    }
}

extern "C" void kernel_launch(void* const* d_in, const int* in_sizes, int n_in,
                              void* d_out, int out_size)
{
    const float* hs   = (const float*)d_in[0];
    const float* mask = (const float*)d_in[1];
    const float* c0k  = (const float*)d_in[2];
    const float* c0v  = (const float*)d_in[3];
    const float* c1k  = (const float*)d_in[4];
    const float* c1v  = (const float*)d_in[5];
    const float* Wq   = (const float*)d_in[6];
    const float* bq   = (const float*)d_in[7];
    const float* Wk   = (const float*)d_in[8];
    const float* bk   = (const float*)d_in[9];
    const float* Wv   = (const float*)d_in[10];
    const float* bv   = (const float*)d_in[11];
    float* out = (float*)d_out;

    dim3 tgrid(HID / 32, HID / 32, 3);
    transpose_w<<<tgrid, dim3(32, 8)>>>(Wq, Wk, Wv);

    dim3 ggrid(MROWS / 128, HID / 128, 3);   // (60, 6, 3)
    qkv_gemm_mma<<<ggrid, 256>>>(hs, bq, bk, bv);

    attn_kernel<<<FULLB * NH, 128>>>(c0k, c0v, c1k, c1v, mask, out);
}

// round 9
// speedup vs baseline: 3.9656x; 1.2926x over previous
#include <cuda_runtime.h>
#include <cstdint>

#define NH 12
#define HD 64
#define HID 768
#define BSC 8
#define FULLB 240
#define LQ 32
#define LEN0 512
#define LEN1 128
#define TOTKV 672
#define MROWS (FULLB*LQ)   // 7680

// Scratch
__device__ float g_q[FULLB*NH*LQ*HD];
__device__ float g_k[FULLB*NH*LQ*HD];
__device__ float g_v[FULLB*NH*LQ*HD];
__device__ float g_wt[3*HID*HID];     // Wt[n][k] = W[k][n]

__device__ __forceinline__ void mma_tf32(float* c, uint32_t a0, uint32_t a1,
                                         uint32_t a2, uint32_t a3,
                                         uint32_t b0, uint32_t b1) {
    asm volatile(
        "mma.sync.aligned.m16n8k8.row.col.f32.tf32.tf32.f32 "
        "{%0,%1,%2,%3}, {%4,%5,%6,%7}, {%8,%9}, {%0,%1,%2,%3};"
        : "+f"(c[0]), "+f"(c[1]), "+f"(c[2]), "+f"(c[3])
        : "r"(a0), "r"(a1), "r"(a2), "r"(a3), "r"(b0), "r"(b1));
}
// round-to-nearest tf32 (returns tf32-valued fp32 bits)
__device__ __forceinline__ uint32_t f2tf(float x) {
    uint32_t r;
    asm("cvt.rna.tf32.f32 %0, %1;" : "=r"(r) : "f"(x));
    return r;
}
__device__ __forceinline__ float f2tff(float x) {
    return __uint_as_float(f2tf(x));
}

// 3xTF32 MMA: near-fp32 precision. a[4] full fp32, b0/b1 full fp32.
__device__ __forceinline__ void mma_tf32_3x(float* c, const float a[4],
                                            float b0, float b1) {
    uint32_t ah[4], al[4];
    #pragma unroll
    for (int i = 0; i < 4; i++) {
        ah[i] = f2tf(a[i]);
        al[i] = __float_as_uint(a[i] - __uint_as_float(ah[i]));
    }
    uint32_t bh0 = f2tf(b0), bh1 = f2tf(b1);
    uint32_t bl0 = __float_as_uint(b0 - __uint_as_float(bh0));
    uint32_t bl1 = __float_as_uint(b1 - __uint_as_float(bh1));
    mma_tf32(c, ah[0], ah[1], ah[2], ah[3], bh0, bh1);
    mma_tf32(c, ah[0], ah[1], ah[2], ah[3], bl0, bl1);
    mma_tf32(c, al[0], al[1], al[2], al[3], bh0, bh1);
}

// ---------------------------------------------------------------------------
// Weight transpose: Wt[n][k] = W[k][n]
// ---------------------------------------------------------------------------
__global__ __launch_bounds__(256) void transpose_w(
    const float* __restrict__ Wq, const float* __restrict__ Wk, const float* __restrict__ Wv)
{
    const float* W = blockIdx.z == 0 ? Wq : blockIdx.z == 1 ? Wk : Wv;
    float* Wt = g_wt + (size_t)blockIdx.z * HID * HID;
    __shared__ float ts[32][33];
    int tx = threadIdx.x, ty = threadIdx.y;
    int x = blockIdx.x * 32 + tx;
    int y0 = blockIdx.y * 32;
    #pragma unroll
    for (int i = 0; i < 4; i++)
        ts[ty + 8 * i][tx] = W[(size_t)(y0 + ty + 8 * i) * HID + x];
    __syncthreads();
    int x2 = blockIdx.y * 32 + tx;
    int y2 = blockIdx.x * 32;
    #pragma unroll
    for (int i = 0; i < 4; i++)
        Wt[(size_t)(y2 + ty + 8 * i) * HID + x2] = ts[tx][ty + 8 * i];
}

// ---------------------------------------------------------------------------
// TF32 mma.sync QKV GEMM: CTA 128x128, 8 warps (2m x 4n).
// Inputs rounded (rna) to tf32 at smem fill - unbiased, ~2x less error than
// the HW truncation path.
// ---------------------------------------------------------------------------
#define KB 32
#define SAS 36

__global__ __launch_bounds__(256) void qkv_gemm_mma(
    const float* __restrict__ A,
    const float* __restrict__ bq, const float* __restrict__ bk, const float* __restrict__ bv)
{
    __shared__ float As[128 * SAS];
    __shared__ float Bs[128 * SAS];

    const int tid = threadIdx.x;
    const int wid = tid >> 5;
    const int lane = tid & 31;
    const int g = lane >> 2;
    const int tig = lane & 3;
    const int wm = wid & 1;
    const int wn = wid >> 1;

    const int z = blockIdx.z;
    const float* bias = z == 0 ? bq : z == 1 ? bk : bv;
    float* out = z == 0 ? g_q : z == 1 ? g_k : g_v;
    const float* Wt = g_wt + (size_t)z * HID * HID;
    const int m0 = blockIdx.x * 128;
    const int n0 = blockIdx.y * 128;

    float c[4][4][4];
    #pragma unroll
    for (int mt = 0; mt < 4; mt++)
        #pragma unroll
        for (int nt = 0; nt < 4; nt++)
            #pragma unroll
            for (int q = 0; q < 4; q++) c[mt][nt][q] = 0.f;

    for (int k0 = 0; k0 < HID; k0 += KB) {
        __syncthreads();
        #pragma unroll
        for (int it = 0; it < 4; it++) {
            int i = tid + it * 256;
            int row = i >> 3;
            int c4 = (i & 7) * 4;
            float4 av = *(const float4*)(A  + (size_t)(m0 + row) * HID + k0 + c4);
            float4 bv4 = *(const float4*)(Wt + (size_t)(n0 + row) * HID + k0 + c4);
            av.x = f2tff(av.x); av.y = f2tff(av.y);
            av.z = f2tff(av.z); av.w = f2tff(av.w);
            bv4.x = f2tff(bv4.x); bv4.y = f2tff(bv4.y);
            bv4.z = f2tff(bv4.z); bv4.w = f2tff(bv4.w);
            *(float4*)(As + row * SAS + c4) = av;
            *(float4*)(Bs + row * SAS + c4) = bv4;
        }
        __syncthreads();

        #pragma unroll
        for (int ks = 0; ks < 4; ks++) {
            const int kb = ks * 8;
            uint32_t bf[4][2];
            #pragma unroll
            for (int nt = 0; nt < 4; nt++) {
                const float* bp = Bs + (wn * 32 + nt * 8 + g) * SAS + kb + tig;
                bf[nt][0] = __float_as_uint(bp[0]);
                bf[nt][1] = __float_as_uint(bp[4]);
            }
            #pragma unroll
            for (int mt = 0; mt < 4; mt++) {
                const float* ap0 = As + (wm * 64 + mt * 16 + g) * SAS + kb + tig;
                const float* ap1 = ap0 + 8 * SAS;
                uint32_t a0 = __float_as_uint(ap0[0]);
                uint32_t a1 = __float_as_uint(ap1[0]);
                uint32_t a2 = __float_as_uint(ap0[4]);
                uint32_t a3 = __float_as_uint(ap1[4]);
                #pragma unroll
                for (int nt = 0; nt < 4; nt++)
                    mma_tf32(c[mt][nt], a0, a1, a2, a3, bf[nt][0], bf[nt][1]);
            }
        }
    }

    #pragma unroll
    for (int mt = 0; mt < 4; mt++) {
        int r0 = m0 + wm * 64 + mt * 16 + g;
        #pragma unroll
        for (int half = 0; half < 2; half++) {
            int r = r0 + half * 8;
            int b = r >> 5;
            int l = r & 31;
            float* obase = out + (((size_t)b * NH) * LQ + l) * HD;
            #pragma unroll
            for (int nt = 0; nt < 4; nt++) {
                int n = n0 + wn * 32 + nt * 8 + tig * 2;
                int h = n >> 6;
                int d = n & 63;
                float2 v;
                v.x = c[mt][nt][half * 2 + 0] + bias[n];
                v.y = c[mt][nt][half * 2 + 1] + bias[n + 1];
                *(float2*)(obase + (size_t)h * LQ * HD + d) = v;
            }
        }
    }
}

// ---------------------------------------------------------------------------
// Attention with 3xTF32 mma.sync for QK and PV (near-fp32 precision).
// One CTA per (b,h), 128 threads = 4 warps.
// ---------------------------------------------------------------------------
#define SD 68

__global__ __launch_bounds__(128) void attn_mma(
    const float* __restrict__ c0k, const float* __restrict__ c0v,
    const float* __restrict__ c1k, const float* __restrict__ c1v,
    const float* __restrict__ mask, float* __restrict__ out)
{
    const int bh = blockIdx.x;
    const int b = bh / NH;
    const int h = bh % NH;

    __shared__ float qp_s[LQ * SD];      // Q staging, then P (scores/probs)
    __shared__ float k_s[64 * SD];       // K tile; O^T staging at the end
    __shared__ float v_s[64 * SD];       // V tile (row-major [kv][d])
    __shared__ float mask_s[TOTKV + 64];
    __shared__ float alpha_s[LQ];
    __shared__ float l_s[LQ];

    const int tid = threadIdx.x;
    const int wid = tid >> 5;
    const int lane = tid & 31;
    const int g = lane >> 2;
    const int tig = lane & 3;
    const int srow = tid >> 2;
    const int q4 = tid & 3;

    {
        const float* qp = g_q + (size_t)bh * (LQ * HD);
        #pragma unroll
        for (int it = 0; it < 4; it++) {
            int i = tid + it * 128;
            int row = i >> 4;
            int c4 = (i & 15) * 4;
            *(float4*)(qp_s + row * SD + c4) = *(const float4*)(qp + row * HD + c4);
        }
    }
    for (int i = tid; i < TOTKV; i += 128)
        mask_s[i] = mask[(size_t)b * TOTKV + i];
    if (tid < 64) mask_s[TOTKV + tid] = 0.f;
    __syncthreads();

    // preload Q A-fragments (full fp32)
    float aq[2][8][4];
    #pragma unroll
    for (int mt = 0; mt < 2; mt++)
        #pragma unroll
        for (int kc = 0; kc < 8; kc++) {
            const float* p = qp_s + (mt * 16 + g) * SD + kc * 8 + tig;
            aq[mt][kc][0] = p[0];
            aq[mt][kc][1] = p[8 * SD];
            aq[mt][kc][2] = p[4];
            aq[mt][kc][3] = p[8 * SD + 4];
        }

    float o[4][4];
    #pragma unroll
    for (int nt = 0; nt < 4; nt++)
        #pragma unroll
        for (int q = 0; q < 4; q++) o[nt][q] = 0.f;

    float m_r = -1e30f, l_r = 0.f;

    for (int t = 0; t < 11; ++t) {
        const float* kp; const float* vp; int rows, kvbase;
        if (t < 8) {
            size_t off = (((size_t)(b % BSC) * NH + h) * LEN0 + t * 64) * HD;
            kp = c0k + off; vp = c0v + off; rows = 64; kvbase = t * 64;
        } else if (t < 10) {
            size_t off = (((size_t)b * NH + h) * LEN1 + (t - 8) * 64) * HD;
            kp = c1k + off; vp = c1v + off; rows = 64; kvbase = LEN0 + (t - 8) * 64;
        } else {
            size_t off = (size_t)bh * (LQ * HD);
            kp = g_k + off; vp = g_v + off; rows = 32; kvbase = LEN0 + LEN1;
        }

        __syncthreads();
        {
            int nld = rows * 16 / 128;
            for (int it = 0; it < nld; it++) {
                int i = tid + it * 128;
                int row = i >> 4;
                int c4 = (i & 15) * 4;
                *(float4*)(k_s + row * SD + c4) = *(const float4*)(kp + row * HD + c4);
                *(float4*)(v_s + row * SD + c4) = *(const float4*)(vp + row * HD + c4);
            }
        }
        __syncthreads();

        // ---- QK (3xTF32): s[mt][nt] ----
        float s[2][2][4];
        #pragma unroll
        for (int mt = 0; mt < 2; mt++)
            #pragma unroll
            for (int nt = 0; nt < 2; nt++)
                #pragma unroll
                for (int q = 0; q < 4; q++) s[mt][nt][q] = 0.f;

        #pragma unroll
        for (int kc = 0; kc < 8; kc++) {
            float b0[2], b1[2];
            #pragma unroll
            for (int nt = 0; nt < 2; nt++) {
                const float* bp = k_s + (wid * 16 + nt * 8 + g) * SD + kc * 8 + tig;
                b0[nt] = bp[0]; b1[nt] = bp[4];
            }
            #pragma unroll
            for (int mt = 0; mt < 2; mt++)
                #pragma unroll
                for (int nt = 0; nt < 2; nt++)
                    mma_tf32_3x(s[mt][nt], aq[mt][kc], b0[nt], b1[nt]);
        }

        // write raw scores to qp_s
        #pragma unroll
        for (int mt = 0; mt < 2; mt++)
            #pragma unroll
            for (int nt = 0; nt < 2; nt++) {
                int cb = wid * 16 + nt * 8 + 2 * tig;
                float* p0 = qp_s + (mt * 16 + g) * SD + cb;
                *(float2*)p0 = make_float2(s[mt][nt][0], s[mt][nt][1]);
                *(float2*)(p0 + 8 * SD) = make_float2(s[mt][nt][2], s[mt][nt][3]);
            }
        __syncthreads();

        // ---- softmax pass ----
        {
            float pv[16];
            float tmax = -1e30f;
            #pragma unroll
            for (int j4 = 0; j4 < 4; j4++) {
                float4 sv = *(const float4*)(qp_s + srow * SD + q4 * 16 + j4 * 4);
                float4 mv = *(const float4*)(mask_s + kvbase + q4 * 16 + j4 * 4);
                float vv[4] = {sv.x * 0.125f + mv.x, sv.y * 0.125f + mv.y,
                               sv.z * 0.125f + mv.z, sv.w * 0.125f + mv.w};
                #pragma unroll
                for (int e = 0; e < 4; e++) {
                    int jc = q4 * 16 + j4 * 4 + e;
                    float val = (jc < rows) ? vv[e] : -1e30f;
                    pv[j4 * 4 + e] = val;
                    tmax = fmaxf(tmax, val);
                }
            }
            tmax = fmaxf(tmax, __shfl_xor_sync(0xffffffffu, tmax, 1));
            tmax = fmaxf(tmax, __shfl_xor_sync(0xffffffffu, tmax, 2));
            float m_new = fmaxf(m_r, tmax);
            float alpha = __expf(m_r - m_new);
            float psum = 0.f;
            #pragma unroll
            for (int j = 0; j < 16; j++) {
                pv[j] = __expf(pv[j] - m_new);
                psum += pv[j];
            }
            psum += __shfl_xor_sync(0xffffffffu, psum, 1);
            psum += __shfl_xor_sync(0xffffffffu, psum, 2);
            l_r = l_r * alpha + psum;
            m_r = m_new;
            #pragma unroll
            for (int j4 = 0; j4 < 4; j4++)
                *(float4*)(qp_s + srow * SD + q4 * 16 + j4 * 4) =
                    make_float4(pv[j4 * 4 + 0], pv[j4 * 4 + 1],
                                pv[j4 * 4 + 2], pv[j4 * 4 + 3]);
            if (q4 == 0) alpha_s[srow] = alpha;
        }
        __syncthreads();

        // ---- PV (3xTF32): O^T[d][q] += V^T[d][kv] * P^T[kv][q] ----
        #pragma unroll
        for (int nt = 0; nt < 4; nt++) {
            float la0 = alpha_s[nt * 8 + 2 * tig];
            float la1 = alpha_s[nt * 8 + 2 * tig + 1];
            o[nt][0] *= la0; o[nt][1] *= la1;
            o[nt][2] *= la0; o[nt][3] *= la1;
        }
        #pragma unroll
        for (int kc = 0; kc < 8; kc++) {
            const float* vb = v_s + (kc * 8 + tig) * SD + wid * 16 + g;
            float av[4];
            av[0] = vb[0];
            av[1] = vb[8];
            av[2] = vb[4 * SD];
            av[3] = vb[4 * SD + 8];
            #pragma unroll
            for (int nt = 0; nt < 4; nt++) {
                const float* pb = qp_s + (nt * 8 + g) * SD + kc * 8 + tig;
                mma_tf32_3x(o[nt], av, pb[0], pb[4]);
            }
        }
    }

    if (q4 == 0) l_s[srow] = l_r;
    __syncthreads();

    // normalize and stage O^T into k_s (stride 33)
    #pragma unroll
    for (int nt = 0; nt < 4; nt++) {
        int q0 = nt * 8 + 2 * tig;
        float il0 = 1.f / l_s[q0];
        float il1 = 1.f / l_s[q0 + 1];
        int d0 = wid * 16 + g;
        k_s[d0 * 33 + q0]     = o[nt][0] * il0;
        k_s[d0 * 33 + q0 + 1] = o[nt][1] * il1;
        k_s[(d0 + 8) * 33 + q0]     = o[nt][2] * il0;
        k_s[(d0 + 8) * 33 + q0 + 1] = o[nt][3] * il1;
    }
    __syncthreads();

    {
        int q = tid >> 2;
        int dp = (tid & 3) * 16;
        float* op = out + ((size_t)(b * LQ + q)) * HID + h * HD + dp;
        #pragma unroll
        for (int j = 0; j < 4; j++) {
            float4 vv;
            vv.x = k_s[(dp + 4 * j + 0) * 33 + q];
            vv.y = k_s[(dp + 4 * j + 1) * 33 + q];
            vv.z = k_s[(dp + 4 * j + 2) * 33 + q];
            vv.w = k_s[(dp + 4 * j + 3) * 33 + q];
            *(float4*)(op + 4 * j) = vv;
        }
    }
}

extern "C" void kernel_launch(void* const* d_in, const int* in_sizes, int n_in,
                              void* d_out, int out_size)
{
    const float* hs   = (const float*)d_in[0];
    const float* mask = (const float*)d_in[1];
    const float* c0k  = (const float*)d_in[2];
    const float* c0v  = (const float*)d_in[3];
    const float* c1k  = (const float*)d_in[4];
    const float* c1v  = (const float*)d_in[5];
    const float* Wq   = (const float*)d_in[6];
    const float* bq   = (const float*)d_in[7];
    const float* Wk   = (const float*)d_in[8];
    const float* bk   = (const float*)d_in[9];
    const float* Wv   = (const float*)d_in[10];
    const float* bv   = (const float*)d_in[11];
    float* out = (float*)d_out;

    dim3 tgrid(HID / 32, HID / 32, 3);
    transpose_w<<<tgrid, dim3(32, 8)>>>(Wq, Wk, Wv);

    dim3 ggrid(MROWS / 128, HID / 128, 3);
    qkv_gemm_mma<<<ggrid, 256>>>(hs, bq, bk, bv);

    attn_mma<<<FULLB * NH, 128>>>(c0k, c0v, c1k, c1v, mask, out);
}

// round 11
// speedup vs baseline: 4.5873x; 1.1568x over previous
#include <cuda_runtime.h>
#include <cstdint>

#define NH 12
#define HD 64
#define HID 768
#define BSC 8
#define FULLB 240
#define LQ 32
#define LEN0 512
#define LEN1 128
#define TOTKV 672
#define MROWS (FULLB*LQ)   // 7680

// Scratch
__device__ float g_q[FULLB*NH*LQ*HD];
__device__ float g_k[FULLB*NH*LQ*HD];
__device__ float g_v[FULLB*NH*LQ*HD];
__device__ float g_wt[3*HID*HID];     // Wt[n][k] = W[k][n]

__device__ __forceinline__ void mma_tf32(float* c, uint32_t a0, uint32_t a1,
                                         uint32_t a2, uint32_t a3,
                                         uint32_t b0, uint32_t b1) {
    asm volatile(
        "mma.sync.aligned.m16n8k8.row.col.f32.tf32.tf32.f32 "
        "{%0,%1,%2,%3}, {%4,%5,%6,%7}, {%8,%9}, {%0,%1,%2,%3};"
        : "+f"(c[0]), "+f"(c[1]), "+f"(c[2]), "+f"(c[3])
        : "r"(a0), "r"(a1), "r"(a2), "r"(a3), "r"(b0), "r"(b1));
}
// round-to-nearest tf32
__device__ __forceinline__ uint32_t f2tf(float x) {
    uint32_t r;
    asm("cvt.rna.tf32.f32 %0, %1;" : "=r"(r) : "f"(x));
    return r;
}
__device__ __forceinline__ float f2tff(float x) {
    return __uint_as_float(f2tf(x));
}

// ---------------------------------------------------------------------------
// Weight transpose: Wt[n][k] = W[k][n]
// ---------------------------------------------------------------------------
__global__ __launch_bounds__(256) void transpose_w(
    const float* __restrict__ Wq, const float* __restrict__ Wk, const float* __restrict__ Wv)
{
    const float* W = blockIdx.z == 0 ? Wq : blockIdx.z == 1 ? Wk : Wv;
    float* Wt = g_wt + (size_t)blockIdx.z * HID * HID;
    __shared__ float ts[32][33];
    int tx = threadIdx.x, ty = threadIdx.y;
    int x = blockIdx.x * 32 + tx;
    int y0 = blockIdx.y * 32;
    #pragma unroll
    for (int i = 0; i < 4; i++)
        ts[ty + 8 * i][tx] = W[(size_t)(y0 + ty + 8 * i) * HID + x];
    __syncthreads();
    int x2 = blockIdx.y * 32 + tx;
    int y2 = blockIdx.x * 32;
    #pragma unroll
    for (int i = 0; i < 4; i++)
        Wt[(size_t)(y2 + ty + 8 * i) * HID + x2] = ts[tx][ty + 8 * i];
}

// ---------------------------------------------------------------------------
// TF32 mma.sync QKV GEMM (R8-proven): CTA 128x128, 8 warps (2m x 4n), rna inputs.
// ---------------------------------------------------------------------------
#define KB 32
#define SAS 36

__global__ __launch_bounds__(256) void qkv_gemm_mma(
    const float* __restrict__ A,
    const float* __restrict__ bq, const float* __restrict__ bk, const float* __restrict__ bv)
{
    __shared__ float As[128 * SAS];
    __shared__ float Bs[128 * SAS];

    const int tid = threadIdx.x;
    const int wid = tid >> 5;
    const int lane = tid & 31;
    const int g = lane >> 2;
    const int tig = lane & 3;
    const int wm = wid & 1;
    const int wn = wid >> 1;

    const int z = blockIdx.z;
    const float* bias = z == 0 ? bq : z == 1 ? bk : bv;
    float* out = z == 0 ? g_q : z == 1 ? g_k : g_v;
    const float* Wt = g_wt + (size_t)z * HID * HID;
    const int m0 = blockIdx.x * 128;
    const int n0 = blockIdx.y * 128;

    float c[4][4][4];
    #pragma unroll
    for (int mt = 0; mt < 4; mt++)
        #pragma unroll
        for (int nt = 0; nt < 4; nt++)
            #pragma unroll
            for (int q = 0; q < 4; q++) c[mt][nt][q] = 0.f;

    for (int k0 = 0; k0 < HID; k0 += KB) {
        __syncthreads();
        #pragma unroll
        for (int it = 0; it < 4; it++) {
            int i = tid + it * 256;
            int row = i >> 3;
            int c4 = (i & 7) * 4;
            float4 av = *(const float4*)(A  + (size_t)(m0 + row) * HID + k0 + c4);
            float4 bv4 = *(const float4*)(Wt + (size_t)(n0 + row) * HID + k0 + c4);
            av.x = f2tff(av.x); av.y = f2tff(av.y);
            av.z = f2tff(av.z); av.w = f2tff(av.w);
            bv4.x = f2tff(bv4.x); bv4.y = f2tff(bv4.y);
            bv4.z = f2tff(bv4.z); bv4.w = f2tff(bv4.w);
            *(float4*)(As + row * SAS + c4) = av;
            *(float4*)(Bs + row * SAS + c4) = bv4;
        }
        __syncthreads();

        #pragma unroll
        for (int ks = 0; ks < 4; ks++) {
            const int kb = ks * 8;
            uint32_t bf[4][2];
            #pragma unroll
            for (int nt = 0; nt < 4; nt++) {
                const float* bp = Bs + (wn * 32 + nt * 8 + g) * SAS + kb + tig;
                bf[nt][0] = __float_as_uint(bp[0]);
                bf[nt][1] = __float_as_uint(bp[4]);
            }
            #pragma unroll
            for (int mt = 0; mt < 4; mt++) {
                const float* ap0 = As + (wm * 64 + mt * 16 + g) * SAS + kb + tig;
                const float* ap1 = ap0 + 8 * SAS;
                uint32_t a0 = __float_as_uint(ap0[0]);
                uint32_t a1 = __float_as_uint(ap1[0]);
                uint32_t a2 = __float_as_uint(ap0[4]);
                uint32_t a3 = __float_as_uint(ap1[4]);
                #pragma unroll
                for (int nt = 0; nt < 4; nt++)
                    mma_tf32(c[mt][nt], a0, a1, a2, a3, bf[nt][0], bf[nt][1]);
            }
        }
    }

    #pragma unroll
    for (int mt = 0; mt < 4; mt++) {
        int r0 = m0 + wm * 64 + mt * 16 + g;
        #pragma unroll
        for (int half = 0; half < 2; half++) {
            int r = r0 + half * 8;
            int b = r >> 5;
            int l = r & 31;
            float* obase = out + (((size_t)b * NH) * LQ + l) * HD;
            #pragma unroll
            for (int nt = 0; nt < 4; nt++) {
                int n = n0 + wn * 32 + nt * 8 + tig * 2;
                int h = n >> 6;
                int d = n & 63;
                float2 v;
                v.x = c[mt][nt][half * 2 + 0] + bias[n];
                v.y = c[mt][nt][half * 2 + 1] + bias[n + 1];
                *(float2*)(obase + (size_t)h * LQ * HD + d) = v;
            }
        }
    }
}

// ---------------------------------------------------------------------------
// Attention, 2-term compensated tf32 MMAs.
// QK: Q pre-rounded (rna, x0.125 folded) -> q.(k_hi + k_lo), 2 MMAs.
// PV: P rounded at softmax write    -> (v_hi + v_lo).p, 2 MMAs.
// One CTA per (b,h), 128 threads = 4 warps.
// ---------------------------------------------------------------------------
#define SD 68

__global__ __launch_bounds__(128) void attn_mma(
    const float* __restrict__ c0k, const float* __restrict__ c0v,
    const float* __restrict__ c1k, const float* __restrict__ c1v,
    const float* __restrict__ mask, float* __restrict__ out)
{
    const int bh = blockIdx.x;
    const int b = bh / NH;
    const int h = bh % NH;

    __shared__ float qp_s[LQ * SD];      // Q staging (rounded), then P
    __shared__ float k_s[64 * SD];       // K tile; O^T staging at the end
    __shared__ float v_s[64 * SD];       // V tile
    __shared__ float mask_s[TOTKV + 64];
    __shared__ float alpha_s[LQ];
    __shared__ float l_s[LQ];

    const int tid = threadIdx.x;
    const int wid = tid >> 5;
    const int lane = tid & 31;
    const int g = lane >> 2;
    const int tig = lane & 3;
    const int srow = tid >> 2;
    const int q4 = tid & 3;

    // load Q (32x64), fold in 1/sqrt(64), round to tf32 once
    {
        const float* qp = g_q + (size_t)bh * (LQ * HD);
        #pragma unroll
        for (int it = 0; it < 4; it++) {
            int i = tid + it * 128;
            int row = i >> 4;
            int c4 = (i & 15) * 4;
            float4 v = *(const float4*)(qp + row * HD + c4);
            v.x = f2tff(v.x * 0.125f); v.y = f2tff(v.y * 0.125f);
            v.z = f2tff(v.z * 0.125f); v.w = f2tff(v.w * 0.125f);
            *(float4*)(qp_s + row * SD + c4) = v;
        }
    }
    for (int i = tid; i < TOTKV; i += 128)
        mask_s[i] = mask[(size_t)b * TOTKV + i];
    if (tid < 64) mask_s[TOTKV + tid] = 0.f;
    __syncthreads();

    // preload Q A-fragments (tf32-valued bits)
    uint32_t aq[2][8][4];
    #pragma unroll
    for (int mt = 0; mt < 2; mt++)
        #pragma unroll
        for (int kc = 0; kc < 8; kc++) {
            const float* p = qp_s + (mt * 16 + g) * SD + kc * 8 + tig;
            aq[mt][kc][0] = __float_as_uint(p[0]);
            aq[mt][kc][1] = __float_as_uint(p[8 * SD]);
            aq[mt][kc][2] = __float_as_uint(p[4]);
            aq[mt][kc][3] = __float_as_uint(p[8 * SD + 4]);
        }

    float o[4][4];
    #pragma unroll
    for (int nt = 0; nt < 4; nt++)
        #pragma unroll
        for (int q = 0; q < 4; q++) o[nt][q] = 0.f;

    float m_r = -1e30f, l_r = 0.f;

    for (int t = 0; t < 11; ++t) {
        const float* kp; const float* vp; int rows, kvbase;
        if (t < 8) {
            size_t off = (((size_t)(b % BSC) * NH + h) * LEN0 + t * 64) * HD;
            kp = c0k + off; vp = c0v + off; rows = 64; kvbase = t * 64;
        } else if (t < 10) {
            size_t off = (((size_t)b * NH + h) * LEN1 + (t - 8) * 64) * HD;
            kp = c1k + off; vp = c1v + off; rows = 64; kvbase = LEN0 + (t - 8) * 64;
        } else {
            size_t off = (size_t)bh * (LQ * HD);
            kp = g_k + off; vp = g_v + off; rows = 32; kvbase = LEN0 + LEN1;
        }

        __syncthreads();
        {
            int nld = rows * 16 / 128;
            for (int it = 0; it < nld; it++) {
                int i = tid + it * 128;
                int row = i >> 4;
                int c4 = (i & 15) * 4;
                *(float4*)(k_s + row * SD + c4) = *(const float4*)(kp + row * HD + c4);
                *(float4*)(v_s + row * SD + c4) = *(const float4*)(vp + row * HD + c4);
            }
        }
        __syncthreads();

        // ---- QK: s = q_tf32 . (k_hi + k_lo), 2 MMAs per (mt,nt,kc) ----
        float s[2][2][4];
        #pragma unroll
        for (int mt = 0; mt < 2; mt++)
            #pragma unroll
            for (int nt = 0; nt < 2; nt++)
                #pragma unroll
                for (int q = 0; q < 4; q++) s[mt][nt][q] = 0.f;

        #pragma unroll
        for (int kc = 0; kc < 8; kc++) {
            #pragma unroll
            for (int nt = 0; nt < 2; nt++) {
                const float* bp = k_s + (wid * 16 + nt * 8 + g) * SD + kc * 8 + tig;
                float b0 = bp[0], b1 = bp[4];
                uint32_t bh0 = f2tf(b0), bh1 = f2tf(b1);
                uint32_t bl0 = __float_as_uint(b0 - __uint_as_float(bh0));
                uint32_t bl1 = __float_as_uint(b1 - __uint_as_float(bh1));
                #pragma unroll
                for (int mt = 0; mt < 2; mt++) {
                    const uint32_t* a = aq[mt][kc];
                    mma_tf32(s[mt][nt], a[0], a[1], a[2], a[3], bh0, bh1);
                    mma_tf32(s[mt][nt], a[0], a[1], a[2], a[3], bl0, bl1);
                }
            }
        }

        // write raw scores to qp_s
        #pragma unroll
        for (int mt = 0; mt < 2; mt++)
            #pragma unroll
            for (int nt = 0; nt < 2; nt++) {
                int cb = wid * 16 + nt * 8 + 2 * tig;
                float* p0 = qp_s + (mt * 16 + g) * SD + cb;
                *(float2*)p0 = make_float2(s[mt][nt][0], s[mt][nt][1]);
                *(float2*)(p0 + 8 * SD) = make_float2(s[mt][nt][2], s[mt][nt][3]);
            }
        __syncthreads();

        // ---- softmax pass (scale already folded into Q) ----
        {
            float pv[16];
            float tmax = -1e30f;
            #pragma unroll
            for (int j4 = 0; j4 < 4; j4++) {
                float4 sv = *(const float4*)(qp_s + srow * SD + q4 * 16 + j4 * 4);
                float4 mv = *(const float4*)(mask_s + kvbase + q4 * 16 + j4 * 4);
                float vv[4] = {sv.x + mv.x, sv.y + mv.y, sv.z + mv.z, sv.w + mv.w};
                #pragma unroll
                for (int e = 0; e < 4; e++) {
                    int jc = q4 * 16 + j4 * 4 + e;
                    float val = (jc < rows) ? vv[e] : -1e30f;
                    pv[j4 * 4 + e] = val;
                    tmax = fmaxf(tmax, val);
                }
            }
            tmax = fmaxf(tmax, __shfl_xor_sync(0xffffffffu, tmax, 1));
            tmax = fmaxf(tmax, __shfl_xor_sync(0xffffffffu, tmax, 2));
            float m_new = fmaxf(m_r, tmax);
            float alpha = __expf(m_r - m_new);
            float psum = 0.f;
            #pragma unroll
            for (int j = 0; j < 16; j++) {
                pv[j] = f2tff(__expf(pv[j] - m_new));   // rounded P
                psum += pv[j];
            }
            psum += __shfl_xor_sync(0xffffffffu, psum, 1);
            psum += __shfl_xor_sync(0xffffffffu, psum, 2);
            l_r = l_r * alpha + psum;
            m_r = m_new;
            #pragma unroll
            for (int j4 = 0; j4 < 4; j4++)
                *(float4*)(qp_s + srow * SD + q4 * 16 + j4 * 4) =
                    make_float4(pv[j4 * 4 + 0], pv[j4 * 4 + 1],
                                pv[j4 * 4 + 2], pv[j4 * 4 + 3]);
            if (q4 == 0) alpha_s[srow] = alpha;
        }
        __syncthreads();

        // ---- PV: O^T += (v_hi + v_lo) . p_tf32, 2 MMAs per (nt,kc) ----
        #pragma unroll
        for (int nt = 0; nt < 4; nt++) {
            float la0 = alpha_s[nt * 8 + 2 * tig];
            float la1 = alpha_s[nt * 8 + 2 * tig + 1];
            o[nt][0] *= la0; o[nt][1] *= la1;
            o[nt][2] *= la0; o[nt][3] *= la1;
        }
        #pragma unroll
        for (int kc = 0; kc < 8; kc++) {
            const float* vb = v_s + (kc * 8 + tig) * SD + wid * 16 + g;
            float a0 = vb[0], a1 = vb[8], a2 = vb[4 * SD], a3 = vb[4 * SD + 8];
            uint32_t h0 = f2tf(a0), h1 = f2tf(a1), h2 = f2tf(a2), h3 = f2tf(a3);
            uint32_t l0 = __float_as_uint(a0 - __uint_as_float(h0));
            uint32_t l1 = __float_as_uint(a1 - __uint_as_float(h1));
            uint32_t l2 = __float_as_uint(a2 - __uint_as_float(h2));
            uint32_t l3 = __float_as_uint(a3 - __uint_as_float(h3));
            #pragma unroll
            for (int nt = 0; nt < 4; nt++) {
                const float* pb = qp_s + (nt * 8 + g) * SD + kc * 8 + tig;
                uint32_t p0 = __float_as_uint(pb[0]);
                uint32_t p1 = __float_as_uint(pb[4]);
                mma_tf32(o[nt], h0, h1, h2, h3, p0, p1);
                mma_tf32(o[nt], l0, l1, l2, l3, p0, p1);
            }
        }
    }

    if (q4 == 0) l_s[srow] = l_r;
    __syncthreads();

    // normalize and stage O^T into k_s (stride 33)
    #pragma unroll
    for (int nt = 0; nt < 4; nt++) {
        int q0 = nt * 8 + 2 * tig;
        float il0 = 1.f / l_s[q0];
        float il1 = 1.f / l_s[q0 + 1];
        int d0 = wid * 16 + g;
        k_s[d0 * 33 + q0]     = o[nt][0] * il0;
        k_s[d0 * 33 + q0 + 1] = o[nt][1] * il1;
        k_s[(d0 + 8) * 33 + q0]     = o[nt][2] * il0;
        k_s[(d0 + 8) * 33 + q0 + 1] = o[nt][3] * il1;
    }
    __syncthreads();

    {
        int q = tid >> 2;
        int dp = (tid & 3) * 16;
        float* op = out + ((size_t)(b * LQ + q)) * HID + h * HD + dp;
        #pragma unroll
        for (int j = 0; j < 4; j++) {
            float4 vv;
            vv.x = k_s[(dp + 4 * j + 0) * 33 + q];
            vv.y = k_s[(dp + 4 * j + 1) * 33 + q];
            vv.z = k_s[(dp + 4 * j + 2) * 33 + q];
            vv.w = k_s[(dp + 4 * j + 3) * 33 + q];
            *(float4*)(op + 4 * j) = vv;
        }
    }
}

extern "C" void kernel_launch(void* const* d_in, const int* in_sizes, int n_in,
                              void* d_out, int out_size)
{
    const float* hs   = (const float*)d_in[0];
    const float* mask = (const float*)d_in[1];
    const float* c0k  = (const float*)d_in[2];
    const float* c0v  = (const float*)d_in[3];
    const float* c1k  = (const float*)d_in[4];
    const float* c1v  = (const float*)d_in[5];
    const float* Wq   = (const float*)d_in[6];
    const float* bq   = (const float*)d_in[7];
    const float* Wk   = (const float*)d_in[8];
    const float* bk   = (const float*)d_in[9];
    const float* Wv   = (const float*)d_in[10];
    const float* bv   = (const float*)d_in[11];
    float* out = (float*)d_out;

    dim3 tgrid(HID / 32, HID / 32, 3);
    transpose_w<<<tgrid, dim3(32, 8)>>>(Wq, Wk, Wv);

    dim3 ggrid(MROWS / 128, HID / 128, 3);
    qkv_gemm_mma<<<ggrid, 256>>>(hs, bq, bk, bv);

    attn_mma<<<FULLB * NH, 128>>>(c0k, c0v, c1k, c1v, mask, out);
}